// round 1
// baseline (speedup 1.0000x reference)
#include <cuda_runtime.h>
#include <cstdint>

// WeightedFeatureInteraction: out[b] = sum_{i<j} w[i,j] * <x[b,i,:], x[b,j,:]>
//   inputs: [B, F*D] fp32, F=64, D=128
//   field_weights: [F, F] fp32
//   out: [B, 1] fp32
//
// Strategy (round 1, CUDA-core fp32):
//   per (b, d): s = sum_{i<j} w_ij * v_i * v_j  with v = x[b,:,d] in registers.
//   Packed f32x2 (FFMA2) handles two d's per thread at double fp32 rate.
//   Block = 2 batch rows x 64 d-pairs = 128 threads. Grid = B/2.

#define NF 64
#define ND 128
#define THREADS 128

__device__ __forceinline__ unsigned long long ffma2(unsigned long long a,
                                                    unsigned long long b,
                                                    unsigned long long c) {
    unsigned long long d;
    asm("fma.rn.f32x2 %0, %1, %2, %3;" : "=l"(d) : "l"(a), "l"(b), "l"(c));
    return d;
}

__device__ __forceinline__ unsigned long long fadd2(unsigned long long a,
                                                    unsigned long long b) {
    unsigned long long d;
    asm("add.rn.f32x2 %0, %1, %2;" : "=l"(d) : "l"(a), "l"(b));
    return d;
}

__device__ __forceinline__ unsigned long long bcast2(float x) {
    unsigned long long d;
    asm("mov.b64 %0, {%1, %1};" : "=l"(d) : "f"(x));
    return d;
}

__global__ void __launch_bounds__(THREADS, 3)
wfi_kernel(const float* __restrict__ inputs,
           const float* __restrict__ fw,
           float* __restrict__ out) {
    __shared__ unsigned long long ws[NF][NF];   // masked w duplicated into f32x2 (32 KB)
    __shared__ float red[4];

    const int tid = threadIdx.x;

    // Prep: masked (j > i) duplicated weights into smem. L2-cached global reads.
    for (int idx = tid; idx < NF * NF; idx += THREADS) {
        int i = idx >> 6;
        int j = idx & 63;
        float wv = (j > i) ? fw[idx] : 0.0f;
        ws[i][j] = bcast2(wv);
    }
    __syncthreads();

    const int b = blockIdx.x * 2 + (tid >> 6);   // batch row for this thread
    const int p = tid & 63;                      // d-pair index (d = 2p, 2p+1)

    const float* xb = inputs + (size_t)b * (NF * ND) + 2 * p;

    // Load v[j] = (x[b,j,2p], x[b,j,2p+1]) -- coalesced across lanes.
    unsigned long long v[NF];
#pragma unroll
    for (int j = 0; j < NF; ++j) {
        v[j] = *(const unsigned long long*)(xb + j * ND);
    }

    // acc = sum_i v_i * (sum_{j>i} w_ij v_j), two interleaved inner chains.
    unsigned long long acc = 0ull;
#pragma unroll
    for (int i = 0; i < NF - 1; ++i) {
        unsigned long long t0 = 0ull, t1 = 0ull;
#pragma unroll
        for (int j = i + 1; j < NF; j += 2) {
            t0 = ffma2(ws[i][j], v[j], t0);
            if (j + 1 < NF) t1 = ffma2(ws[i][j + 1], v[j + 1], t1);
        }
        acc = ffma2(v[i], fadd2(t0, t1), acc);
    }

    // Horizontal: acc.x + acc.y, then reduce 64 threads per batch row.
    float2 a2 = *(float2*)&acc;
    float s = a2.x + a2.y;
#pragma unroll
    for (int off = 16; off > 0; off >>= 1)
        s += __shfl_xor_sync(0xFFFFFFFFu, s, off);

    const int wid = tid >> 5;
    if ((tid & 31) == 0) red[wid] = s;
    __syncthreads();

    if (tid == 0)  out[b] = red[0] + red[1];
    if (tid == 64) out[b] = red[2] + red[3];
}

extern "C" void kernel_launch(void* const* d_in, const int* in_sizes, int n_in,
                              void* d_out, int out_size) {
    const float* inputs = (const float*)d_in[0];
    const float* fw     = (const float*)d_in[1];
    float* out          = (float*)d_out;

    int B = in_sizes[0] / (NF * ND);
    wfi_kernel<<<B / 2, THREADS>>>(inputs, fw, out);
}